// round 2
// baseline (speedup 1.0000x reference)
#include <cuda_runtime.h>

#define THREADS 512
#define EPS_RMS 1e-5f

// ---------------------------------------------------------------------------
// Specialized kernel: E experts compile-time, ITERS float4-chunks per thread.
// One block per token row. output_residual kept in registers between the
// accumulate phase and the normalize phase -> each gmem byte touched once.
// ---------------------------------------------------------------------------
template <int E, int ITERS>
__global__ __launch_bounds__(THREADS)
void moe_ar_rmsnorm_kernel(const float* __restrict__ residual,
                           const float* __restrict__ norm_weight,
                           const float* __restrict__ scale_input,
                           const float* __restrict__ act,      // [E, T, H]
                           const float* __restrict__ token_in, // [T, H]
                           float* __restrict__ hidden,         // [T, H]
                           float* __restrict__ out_res,        // [T, H] or null
                           int T, int H)
{
    const int t   = blockIdx.x;
    const int tid = threadIdx.x;
    const size_t row_off      = (size_t)t * H;
    const size_t plane_stride = (size_t)T * H;

    // per-token expert scales (uniform across block; L2/L1 cached)
    float s[E];
#pragma unroll
    for (int e = 0; e < E; ++e)
        s[e] = __ldg(scale_input + (size_t)e * T + t);

    float4 r[ITERS];
    float ssq = 0.f;

#pragma unroll
    for (int it = 0; it < ITERS; ++it) {
        const int    idx4 = tid + it * THREADS;        // float4 index in row
        const size_t off  = row_off + (size_t)idx4 * 4;

        float4 acc = *reinterpret_cast<const float4*>(residual + off);
        float4 tk  = *reinterpret_cast<const float4*>(token_in + off);
        acc.x += tk.x; acc.y += tk.y; acc.z += tk.z; acc.w += tk.w;

#pragma unroll
        for (int e = 0; e < E; ++e) {
            float4 a = *reinterpret_cast<const float4*>(act + (size_t)e * plane_stride + off);
            acc.x = fmaf(a.x, s[e], acc.x);
            acc.y = fmaf(a.y, s[e], acc.y);
            acc.z = fmaf(a.z, s[e], acc.z);
            acc.w = fmaf(a.w, s[e], acc.w);
        }
        r[it] = acc;
        ssq = fmaf(acc.x, acc.x, ssq);
        ssq = fmaf(acc.y, acc.y, ssq);
        ssq = fmaf(acc.z, acc.z, ssq);
        ssq = fmaf(acc.w, acc.w, ssq);
    }

    // ---- block reduction of sum-of-squares ----
    __shared__ float smem[THREADS / 32];
    __shared__ float s_inv;
#pragma unroll
    for (int o = 16; o > 0; o >>= 1)
        ssq += __shfl_xor_sync(0xFFFFFFFFu, ssq, o);
    if ((tid & 31) == 0) smem[tid >> 5] = ssq;
    __syncthreads();
    if (tid == 0) {
        float tot = 0.f;
#pragma unroll
        for (int w = 0; w < THREADS / 32; ++w) tot += smem[w];
        s_inv = rsqrtf(tot / (float)H + EPS_RMS);
    }
    __syncthreads();
    const float inv = s_inv;

    // ---- write both outputs ----
#pragma unroll
    for (int it = 0; it < ITERS; ++it) {
        const int    idx4 = tid + it * THREADS;
        const size_t off  = row_off + (size_t)idx4 * 4;

        float4 w4 = *reinterpret_cast<const float4*>(norm_weight + (size_t)idx4 * 4);
        float4 rv = r[it];
        if (out_res)
            *reinterpret_cast<float4*>(out_res + off) = rv;

        float4 h;
        h.x = rv.x * inv * w4.x;
        h.y = rv.y * inv * w4.y;
        h.z = rv.z * inv * w4.z;
        h.w = rv.w * inv * w4.w;
        *reinterpret_cast<float4*>(hidden + off) = h;
    }
}

// ---------------------------------------------------------------------------
// Generic fallback (runtime E, arbitrary H multiple of 4): writes out_res to
// gmem in pass 1, re-reads it (L2 hit) for the normalize pass.
// ---------------------------------------------------------------------------
__global__ __launch_bounds__(THREADS)
void moe_ar_rmsnorm_generic(const float* __restrict__ residual,
                            const float* __restrict__ norm_weight,
                            const float* __restrict__ scale_input,
                            const float* __restrict__ act,
                            const float* __restrict__ token_in,
                            float* __restrict__ hidden,
                            float* __restrict__ out_res,
                            int T, int H, int E)
{
    const int t   = blockIdx.x;
    const int tid = threadIdx.x;
    const size_t row_off      = (size_t)t * H;
    const size_t plane_stride = (size_t)T * H;
    const int nvec = H >> 2;

    float ssq = 0.f;
    for (int i = tid; i < nvec; i += THREADS) {
        const size_t off = row_off + (size_t)i * 4;
        float4 acc = *reinterpret_cast<const float4*>(residual + off);
        float4 tk  = *reinterpret_cast<const float4*>(token_in + off);
        acc.x += tk.x; acc.y += tk.y; acc.z += tk.z; acc.w += tk.w;
        for (int e = 0; e < E; ++e) {
            float se = __ldg(scale_input + (size_t)e * T + t);
            float4 a = *reinterpret_cast<const float4*>(act + (size_t)e * plane_stride + off);
            acc.x = fmaf(a.x, se, acc.x);
            acc.y = fmaf(a.y, se, acc.y);
            acc.z = fmaf(a.z, se, acc.z);
            acc.w = fmaf(a.w, se, acc.w);
        }
        *reinterpret_cast<float4*>(out_res + off) = acc;
        ssq += acc.x*acc.x + acc.y*acc.y + acc.z*acc.z + acc.w*acc.w;
    }

    __shared__ float smem[THREADS / 32];
    __shared__ float s_inv;
#pragma unroll
    for (int o = 16; o > 0; o >>= 1)
        ssq += __shfl_xor_sync(0xFFFFFFFFu, ssq, o);
    if ((tid & 31) == 0) smem[tid >> 5] = ssq;
    __syncthreads();
    if (tid == 0) {
        float tot = 0.f;
        for (int w = 0; w < THREADS / 32; ++w) tot += smem[w];
        s_inv = rsqrtf(tot / (float)H + EPS_RMS);
    }
    __syncthreads();
    const float inv = s_inv;

    for (int i = tid; i < nvec; i += THREADS) {
        const size_t off = row_off + (size_t)i * 4;
        float4 rv = *reinterpret_cast<const float4*>(out_res + off);
        float4 w4 = *reinterpret_cast<const float4*>(norm_weight + (size_t)i * 4);
        float4 h;
        h.x = rv.x * inv * w4.x;
        h.y = rv.y * inv * w4.y;
        h.z = rv.z * inv * w4.z;
        h.w = rv.w * inv * w4.w;
        *reinterpret_cast<float4*>(hidden + off) = h;
    }
}

extern "C" void kernel_launch(void* const* d_in, const int* in_sizes, int n_in,
                              void* d_out, int out_size)
{
    const float* residual  = (const float*)d_in[0];
    const float* weight    = (const float*)d_in[1];
    const float* scales    = (const float*)d_in[2];
    const float* act       = (const float*)d_in[3];
    const float* token_in  = (const float*)d_in[4];

    const int H = in_sizes[1];                 // norm_weight
    const int T = in_sizes[0] / H;             // residual [T,H]
    const int E = in_sizes[2] / T;             // scale_input [E,T]

    float* hidden  = (float*)d_out;
    float* out_res = (out_size >= 2 * T * H) ? ((float*)d_out + (size_t)T * H)
                                             : nullptr;

    if (E == 8 && H == THREADS * 4 * 2) {
        // bench shapes: E=8, H=4096
        moe_ar_rmsnorm_kernel<8, 2><<<T, THREADS>>>(
            residual, weight, scales, act, token_in, hidden, out_res, T, H);
    } else if (E == 8 && H == THREADS * 4) {
        moe_ar_rmsnorm_kernel<8, 1><<<T, THREADS>>>(
            residual, weight, scales, act, token_in, hidden, out_res, T, H);
    } else {
        float* res_target = out_res ? out_res : hidden; // degenerate fallback
        moe_ar_rmsnorm_generic<<<T, THREADS>>>(
            residual, weight, scales, act, token_in, hidden, res_target, T, H, E);
    }
}